// round 16
// baseline (speedup 1.0000x reference)
#include <cuda_runtime.h>
#include <math.h>
#include <stdint.h>

#define N_NODES 20000
#define N_EDGES 320000
#define IN_DIM  64
#define EMB     128
#define OUT_DIM 10
#define HID     512
#define RATIO_F 0.25
#define EPSF    1e-20f

// ---------------- scratch (static, no allocs) ----------------
__device__ float g_h0[N_NODES*EMB];
__device__ float g_h1[N_NODES*EMB];
__device__ float g_agg[N_NODES*EMB];
__device__ float g_Afac[N_NODES*HID];
__device__ float g_Bfac[N_NODES*HID];
__device__ float g_pe[N_EDGES];        // slot-ordered
__device__ float g_Tperm[N_EDGES];     // slot-ordered
__device__ int   g_counts[N_NODES];
__device__ int   g_rowptr[N_NODES+1];
__device__ int   g_cursor[N_NODES];
__device__ int   g_srcs[N_EDGES];
__device__ int   g_dsts[N_EDGES];
__device__ int   g_eids[N_EDGES];
__device__ double g_sum8[8], g_sumsq8[8];
__device__ float  g_pmin, g_pmax;
__device__ float  g_mean, g_invstd, g_csum;
__device__ double g_Ssum[32];
__device__ unsigned int g_barc;
__device__ volatile unsigned int g_barg;
__device__ double g_colsum[EMB];
// transposed + bf16-split weights: Wt[n][k], packed as u32 pairs (k fast, 2 bf16/u32)
__device__ unsigned int g_Wth[HID*EMB/2];
__device__ unsigned int g_Wtl[HID*EMB/2];

// ---------------- bf16 split helpers ----------------
__device__ __forceinline__ unsigned bf16rn(float f) {
    unsigned u = __float_as_uint(f);
    return (u + 0x7fffu + ((u >> 16) & 1u)) >> 16;
}
__device__ __forceinline__ void split2(float f, unsigned& hi, unsigned& lo) {
    hi = bf16rn(f);
    float fl = f - __uint_as_float(hi << 16);
    lo = bf16rn(fl);
}

// ---------------- init ----------------
__global__ void init_kernel() {
    int i = blockIdx.x*blockDim.x + threadIdx.x;
    int nt = gridDim.x*blockDim.x;
    for (int k = i; k < N_NODES; k += nt) { g_counts[k] = 0; g_cursor[k] = 0; }
    if (i < EMB) g_colsum[i] = 0.0;
    if (i < 32)  g_Ssum[i]   = 0.0;
    if (i < 8)   { g_sum8[i] = 0.0; g_sumsq8[i] = 0.0; }
    if (i == 0) {
        g_pmin =  3.0e38f; g_pmax = -3.0e38f;
        g_barc = 0u; g_barg = 0u;
    }
}

// ---------------- CSR build ----------------
__global__ void hist_kernel(const int* __restrict__ dst) {
    int i = blockIdx.x*blockDim.x + threadIdx.x;
    int nt = gridDim.x*blockDim.x;
    for (int e = i; e < N_EDGES; e += nt) atomicAdd(&g_counts[dst[e]], 1);
}

__global__ void scan_kernel() {
    __shared__ int s[1024];
    const int CH = (N_NODES + 1023) / 1024;  // 20
    int t = threadIdx.x;
    int lsum = 0;
    for (int i = 0; i < CH; i++) {
        int idx = t*CH + i;
        if (idx < N_NODES) lsum += g_counts[idx];
    }
    s[t] = lsum; __syncthreads();
    for (int off = 1; off < 1024; off <<= 1) {
        int v = (t >= off) ? s[t-off] : 0;
        __syncthreads();
        s[t] += v;
        __syncthreads();
    }
    int run = s[t] - lsum;
    for (int i = 0; i < CH; i++) {
        int idx = t*CH + i;
        if (idx < N_NODES) { g_rowptr[idx] = run; run += g_counts[idx]; }
    }
    if (t == 1023) g_rowptr[N_NODES] = s[1023];
}

__global__ void fill_kernel(const int* __restrict__ src, const int* __restrict__ dst) {
    int i = blockIdx.x*blockDim.x + threadIdx.x;
    int nt = gridDim.x*blockDim.x;
    for (int e = i; e < N_EDGES; e += nt) {
        int d = dst[e];
        int pos = atomicAdd(&g_cursor[d], 1);
        int slot = g_rowptr[d] + pos;
        g_srcs[slot] = src[e];
        g_dsts[slot] = d;
        g_eids[slot] = e;
    }
}

// ---------------- aggregation: warp per node, float4, unroll 4 ----------------
// Tw (if non-null) is slot-ordered (g_Tperm).
__global__ void agg_kernel(const float* __restrict__ h, float* __restrict__ out,
                           const float* __restrict__ Tw, int dim) {
    int warp = threadIdx.x >> 5, lane = threadIdx.x & 31;
    int n = blockIdx.x * 8 + warp;
    if (n >= N_NODES) return;
    int vdim = dim >> 2;
    bool active = lane < vdim;
    const float4* __restrict__ h4 = (const float4*)h;
    int beg = g_rowptr[n], end = g_rowptr[n+1];
    float4 a0 = {0,0,0,0}, a1 = a0, a2 = a0, a3 = a0;
    int j = beg;
    for (; j + 4 <= end; j += 4) {
        int s0 = g_srcs[j], s1 = g_srcs[j+1], s2 = g_srcs[j+2], s3 = g_srcs[j+3];
        float w0 = 1.f, w1 = 1.f, w2 = 1.f, w3 = 1.f;
        if (Tw) { w0 = Tw[j]; w1 = Tw[j+1]; w2 = Tw[j+2]; w3 = Tw[j+3]; }
        if (active) {
            float4 v0 = h4[s0*vdim + lane];
            float4 v1 = h4[s1*vdim + lane];
            float4 v2 = h4[s2*vdim + lane];
            float4 v3 = h4[s3*vdim + lane];
            a0.x = fmaf(w0, v0.x, a0.x); a0.y = fmaf(w0, v0.y, a0.y);
            a0.z = fmaf(w0, v0.z, a0.z); a0.w = fmaf(w0, v0.w, a0.w);
            a1.x = fmaf(w1, v1.x, a1.x); a1.y = fmaf(w1, v1.y, a1.y);
            a1.z = fmaf(w1, v1.z, a1.z); a1.w = fmaf(w1, v1.w, a1.w);
            a2.x = fmaf(w2, v2.x, a2.x); a2.y = fmaf(w2, v2.y, a2.y);
            a2.z = fmaf(w2, v2.z, a2.z); a2.w = fmaf(w2, v2.w, a2.w);
            a3.x = fmaf(w3, v3.x, a3.x); a3.y = fmaf(w3, v3.y, a3.y);
            a3.z = fmaf(w3, v3.z, a3.z); a3.w = fmaf(w3, v3.w, a3.w);
        }
    }
    for (; j < end; j++) {
        int s0 = g_srcs[j];
        float w0 = Tw ? Tw[j] : 1.f;
        if (active) {
            float4 v0 = h4[s0*vdim + lane];
            a0.x = fmaf(w0, v0.x, a0.x); a0.y = fmaf(w0, v0.y, a0.y);
            a0.z = fmaf(w0, v0.z, a0.z); a0.w = fmaf(w0, v0.w, a0.w);
        }
    }
    a0.x += a1.x + a2.x + a3.x;
    a0.y += a1.y + a2.y + a3.y;
    a0.z += a1.z + a2.z + a3.z;
    a0.w += a1.w + a2.w + a3.w;
    if (active) ((float4*)out)[n*vdim + lane] = a0;
}

// ---------------- W prep: transpose + bf16 split ----------------
__global__ void w_prep(const float* __restrict__ W, int K, int N_w) {
    int kp2 = K >> 1;
    int total = N_w * kp2;
    int nt = gridDim.x * blockDim.x;
    for (int idx = blockIdx.x*blockDim.x + threadIdx.x; idx < total; idx += nt) {
        int n  = idx / kp2;
        int kp = idx - n*kp2;
        int k  = kp << 1;
        unsigned h0, l0, h1, l1;
        split2(W[(size_t)k*N_w + n],     h0, l0);
        split2(W[(size_t)(k+1)*N_w + n], h1, l1);
        g_Wth[idx] = h0 | (h1 << 16);
        g_Wtl[idx] = l0 | (l1 << 16);
    }
}

// ---------------- bf16 tensor-core GEMM (R13-proven) ----------------
__device__ __forceinline__ void mma_bf16(float* c, unsigned a0, unsigned a1,
                                         unsigned a2, unsigned a3,
                                         unsigned b0, unsigned b1) {
    asm volatile(
        "mma.sync.aligned.m16n8k16.row.col.f32.bf16.bf16.f32 "
        "{%0,%1,%2,%3}, {%4,%5,%6,%7}, {%8,%9}, {%0,%1,%2,%3};"
        : "+f"(c[0]), "+f"(c[1]), "+f"(c[2]), "+f"(c[3])
        : "r"(a0), "r"(a1), "r"(a2), "r"(a3), "r"(b0), "r"(b1));
}

__global__ __launch_bounds__(256)
void gemm_bf16(const float* __restrict__ X, const float* __restrict__ Y,
               const float* __restrict__ bias, float* __restrict__ C,
               int M, int K, int N_w, int do_relu) {
    extern __shared__ unsigned int sm[];
    const int KP2 = (K + 8) >> 1;
    unsigned int* Ah = sm;
    unsigned int* Al = Ah + 128*KP2;
    unsigned int* Bh = Al + 128*KP2;
    unsigned int* Bl = Bh + 128*KP2;
    const int tid = threadIdx.x;
    const int lane = tid & 31, wid = tid >> 5;
    const int row0 = blockIdx.y << 7;
    const int col0 = blockIdx.x << 7;
    const int kp2 = K >> 1;

    for (int idx = tid; idx < 128*kp2; idx += 256) {
        int nl = idx / kp2;
        int kp = idx - nl*kp2;
        unsigned src = (unsigned)((col0 + nl)*kp2 + kp);
        Bh[nl*KP2 + kp] = g_Wth[src];
        Bl[nl*KP2 + kp] = g_Wtl[src];
    }
    {
        int kq4 = K >> 2;
        for (int idx = tid; idx < 128*kq4; idx += 256) {
            int m  = idx / kq4;
            int kq = idx - m*kq4;
            int k  = kq << 2;
            int gr = row0 + m;
            float4 v = {0.f,0.f,0.f,0.f};
            if (gr < M) {
                v = *reinterpret_cast<const float4*>(X + (size_t)gr*K + k);
                if (Y) {
                    float4 y = *reinterpret_cast<const float4*>(Y + (size_t)gr*K + k);
                    v.x += y.x; v.y += y.y; v.z += y.z; v.w += y.w;
                }
            }
            unsigned h0,l0,h1,l1,h2,l2,h3,l3;
            split2(v.x, h0, l0); split2(v.y, h1, l1);
            split2(v.z, h2, l2); split2(v.w, h3, l3);
            int o = m*KP2 + (kq << 1);
            Ah[o]   = h0 | (h1 << 16);
            Ah[o+1] = h2 | (h3 << 16);
            Al[o]   = l0 | (l1 << 16);
            Al[o+1] = l2 | (l3 << 16);
        }
    }
    __syncthreads();

    const int warp_m = wid >> 1, warp_n = wid & 1;
    const int rbase = warp_m << 5;
    const int nbase = warp_n << 6;
    const int g = lane >> 2, tg = lane & 3;
    const int ksteps = K >> 4;

    float c[2][8][4];
#pragma unroll
    for (int mt = 0; mt < 2; mt++)
#pragma unroll
        for (int nt = 0; nt < 8; nt++)
#pragma unroll
            for (int q = 0; q < 4; q++) c[mt][nt][q] = 0.f;

#pragma unroll
    for (int p = 0; p < 3; p++) {
        const unsigned int* Ap = (p == 2) ? Al : Ah;
        const unsigned int* Bp = (p == 1) ? Bl : Bh;
        for (int ks = 0; ks < ksteps; ks++) {
            int kb = (ks << 3) + tg;
            unsigned a[2][4];
#pragma unroll
            for (int mt = 0; mt < 2; mt++) {
                int r0 = rbase + (mt << 4) + g;
                a[mt][0] = Ap[r0*KP2 + kb];
                a[mt][1] = Ap[(r0+8)*KP2 + kb];
                a[mt][2] = Ap[r0*KP2 + kb + 4];
                a[mt][3] = Ap[(r0+8)*KP2 + kb + 4];
            }
            unsigned b[8][2];
#pragma unroll
            for (int nt = 0; nt < 8; nt++) {
                int n0 = nbase + (nt << 3) + g;
                b[nt][0] = Bp[n0*KP2 + kb];
                b[nt][1] = Bp[n0*KP2 + kb + 4];
            }
#pragma unroll
            for (int mt = 0; mt < 2; mt++)
#pragma unroll
                for (int nt = 0; nt < 8; nt++)
                    mma_bf16(c[mt][nt], a[mt][0], a[mt][1], a[mt][2], a[mt][3],
                             b[nt][0], b[nt][1]);
        }
    }

#pragma unroll
    for (int mt = 0; mt < 2; mt++) {
        int gr0 = row0 + rbase + (mt << 4) + g;
#pragma unroll
        for (int nt = 0; nt < 8; nt++) {
            int gc = col0 + nbase + (nt << 3) + (tg << 1);
            float bx = 0.f, by = 0.f;
            if (bias) { bx = bias[gc]; by = bias[gc+1]; }
            float v0 = c[mt][nt][0] + bx;
            float v1 = c[mt][nt][1] + by;
            float v2 = c[mt][nt][2] + bx;
            float v3 = c[mt][nt][3] + by;
            if (do_relu) {
                v0 = fmaxf(v0, 0.f); v1 = fmaxf(v1, 0.f);
                v2 = fmaxf(v2, 0.f); v3 = fmaxf(v3, 0.f);
            }
            if (gr0 < M)
                *reinterpret_cast<float2*>(C + (size_t)gr0*N_w + gc) = make_float2(v0, v1);
            if (gr0 + 8 < M)
                *reinterpret_cast<float2*>(C + (size_t)(gr0+8)*N_w + gc) = make_float2(v2, v3);
        }
    }
}

// ---------------- pe min/max atomics ----------------
__device__ void atomicMaxF(float* addr, float v) {
    int* ai = (int*)addr; int old = *ai;
    while (__int_as_float(old) < v) {
        int assumed = old;
        old = atomicCAS(ai, assumed, __float_as_int(v));
        if (old == assumed) break;
    }
}
__device__ void atomicMinF(float* addr, float v) {
    int* ai = (int*)addr; int old = *ai;
    while (__int_as_float(old) > v) {
        int assumed = old;
        old = atomicCAS(ai, assumed, __float_as_int(v));
        if (old == assumed) break;
    }
}

// ---------------- edge attention + fused stats (slot-ordered) ----------------
// Block = 256 contiguous CSR slots; same-dst runs -> B-row reuse in L1.
__global__ __launch_bounds__(256)
void edge_pe_kernel(const float* __restrict__ b1, const float* __restrict__ W2,
                    const float* __restrict__ b2) {
    const int lane = threadIdx.x & 31, warp = threadIdx.x >> 5;
    const int base = blockIdx.x*256 + warp*32;
    const float4* b1p = reinterpret_cast<const float4*>(b1);
    const float4* W2p = reinterpret_cast<const float4*>(W2);
    float4 b1r[4], w2r[4];
#pragma unroll
    for (int j = 0; j < 4; j++) {
        b1r[j] = b1p[lane + 32*j];
        w2r[j] = W2p[lane + 32*j];
    }
    float b2v = b2[0];
    double lsum = 0.0, lsq = 0.0;
    float mn = 3.0e38f, mx = -3.0e38f;
    for (int i = 0; i < 32; i++) {
        int slot = base + i;
        if (slot >= N_EDGES) break;
        int s = g_srcs[slot], d = g_dsts[slot];
        const float4* Ap = reinterpret_cast<const float4*>(&g_Afac[s*HID]);
        const float4* Bp = reinterpret_cast<const float4*>(&g_Bfac[d*HID]);
        float acc = 0.f;
#pragma unroll
        for (int j = 0; j < 4; j++) {
            int idx = lane + 32*j;
            float4 a = Ap[idx], b = Bp[idx];
            float z0 = fmaxf(a.x + b.x + b1r[j].x, 0.f);
            float z1 = fmaxf(a.y + b.y + b1r[j].y, 0.f);
            float z2 = fmaxf(a.z + b.z + b1r[j].z, 0.f);
            float z3 = fmaxf(a.w + b.w + b1r[j].w, 0.f);
            acc += z0*w2r[j].x + z1*w2r[j].y + z2*w2r[j].z + z3*w2r[j].w;
        }
#pragma unroll
        for (int off = 16; off > 0; off >>= 1)
            acc += __shfl_xor_sync(0xffffffffu, acc, off);
        if (lane == 0) {
            float pe = acc + b2v;
            g_pe[slot] = pe;
            lsum += pe; lsq += (double)pe*pe;
            mn = fminf(mn, pe); mx = fmaxf(mx, pe);
        }
    }
    __shared__ double ssum[8], ssq[8];
    __shared__ float smn[8], smx[8];
    if (lane == 0) { ssum[warp] = lsum; ssq[warp] = lsq; smn[warp] = mn; smx[warp] = mx; }
    __syncthreads();
    if (threadIdx.x == 0) {
        double ts = 0.0, tq = 0.0; float tmn = 3.0e38f, tmx = -3.0e38f;
#pragma unroll
        for (int w = 0; w < 8; w++) {
            ts += ssum[w]; tq += ssq[w];
            tmn = fminf(tmn, smn[w]); tmx = fmaxf(tmx, smx[w]);
        }
        atomicAdd(&g_sum8[blockIdx.x & 7], ts);
        atomicAdd(&g_sumsq8[blockIdx.x & 7], tq);
        atomicMinF(&g_pmin, tmn);
        atomicMaxF(&g_pmax, tmx);
    }
}

__global__ void finalize_kernel() {
    double s = 0.0, q = 0.0;
    for (int i = 0; i < 8; i++) { s += g_sum8[i]; q += g_sumsq8[i]; }
    double mean = s / (double)N_EDGES;
    double var = (q - s*s/(double)N_EDGES) / (double)(N_EDGES - 1);
    double istd = 1.0 / sqrt(var);
    g_mean = (float)mean;
    g_invstd = (float)istd;
    g_csum = (float)(((double)g_pmin + (double)g_pmax - 2.0*mean) * istd);
}

// ---------------- Sinkhorn: fused delta0, few blocks (cheap grid barrier) ----------------
#define SK_BLOCKS 33
#define SK_THREADS 256
#define SK_PER 38

__global__ void sinkhorn_kernel(const float* __restrict__ u) {
    const int stride = SK_BLOCKS * SK_THREADS;   // 8448
    const int tid = blockIdx.x*blockDim.x + threadIdx.x;
    const float mean = g_mean, istd = g_invstd, cs = g_csum;
    float dv[SK_PER];
#pragma unroll
    for (int i = 0; i < SK_PER; i++) {
        int e = tid + i*stride;
        if (e < N_EDGES) {
            float pe = g_pe[e];
            float uu = u[g_eids[e]];
            float gmb = -logf(-logf(uu + EPSF) + EPSF);
            float att = (pe - mean) * istd;
            dv[i] = 2.f*(att + gmb) - cs;    // TEMP=1, NOISE=1
        } else {
            dv[i] = -1.0e30f;                 // sigmoid -> 0 for pad
        }
    }
    __shared__ double sred[SK_THREADS];
    double K = 0.0;
    double Sfin = 0.0;
    for (int it = 0; it < 30; it++) {
        float Kf = (float)K;
        double s = 0.0;
#pragma unroll
        for (int i = 0; i < SK_PER; i++)
            s += 1.0f / (1.0f + __expf(-(dv[i] + Kf)));
        sred[threadIdx.x] = s;
        __syncthreads();
        for (int off = SK_THREADS/2; off > 0; off >>= 1) {
            if (threadIdx.x < off) sred[threadIdx.x] += sred[threadIdx.x + off];
            __syncthreads();
        }
        if (threadIdx.x == 0) atomicAdd(&g_Ssum[it], sred[0]);
        __threadfence();
        __syncthreads();
        if (threadIdx.x == 0) {
            unsigned my = atomicAdd(&g_barc, 1u);
            if (my == SK_BLOCKS - 1) {
                g_barc = 0u;
                __threadfence();
                g_barg = (unsigned)(it + 1);
            } else {
                while (g_barg < (unsigned)(it + 1)) { }
            }
        }
        __syncthreads();
        __threadfence();
        double S1 = ((volatile double*)g_Ssum)[it];
        if (it == 29) { Sfin = S1; break; }
        double S0 = (double)N_EDGES - S1;
        K += log(S0 / S1) + log(RATIO_F / (1.0 - RATIO_F));
        __syncthreads();
    }
    float Kf = (float)K;
    float scale = (float)(((double)N_EDGES * RATIO_F) / Sfin);
#pragma unroll
    for (int i = 0; i < SK_PER; i++) {
        int e = tid + i*stride;
        if (e < N_EDGES)
            g_Tperm[e] = scale / (1.f + __expf(-(dv[i] + Kf)));  // slot-ordered
    }
}

// ---------------- mean pool + head ----------------
__global__ void colsum_kernel(const float* __restrict__ h) {
    int t = threadIdx.x;
    double acc = 0.0;
    for (int r = blockIdx.x; r < N_NODES; r += gridDim.x)
        acc += h[r*EMB + t];
    atomicAdd(&g_colsum[t], acc);
}

__global__ void head_kernel(const float* __restrict__ head_W,
                            const float* __restrict__ head_b,
                            float* __restrict__ out) {
    __shared__ float rep[EMB];
    int t = threadIdx.x;
    rep[t] = (float)(g_colsum[t] / (double)N_NODES);
    __syncthreads();
    if (t < OUT_DIM) {
        float a = head_b[t];
        for (int d = 0; d < EMB; d++) a += rep[d] * head_W[d*OUT_DIM + t];
        out[t] = a;
    }
}

// ---------------- launch ----------------
extern "C" void kernel_launch(void* const* d_in, const int* in_sizes, int n_in,
                              void* d_out, int out_size) {
    const float* x       = (const float*)d_in[0];
    const int*   ei      = (const int*)  d_in[1];
    const float* u       = (const float*)d_in[2];
    const float* enc_W0  = (const float*)d_in[3];
    const float* enc_b0  = (const float*)d_in[4];
    const float* enc_W   = (const float*)d_in[5];
    const float* enc_b   = (const float*)d_in[6];
    const float* ea_W1   = (const float*)d_in[7];
    const float* ea_b1   = (const float*)d_in[8];
    const float* ea_W2   = (const float*)d_in[9];
    const float* ea_b2   = (const float*)d_in[10];
    const float* cls_W0  = (const float*)d_in[11];
    const float* cls_b0  = (const float*)d_in[12];
    const float* cls_W   = (const float*)d_in[13];
    const float* cls_b   = (const float*)d_in[14];
    const float* head_W  = (const float*)d_in[15];
    const float* head_b  = (const float*)d_in[16];
    const int* src = ei;
    const int* dst = ei + N_EDGES;

    // GB300/ATS: resolve real device addresses of __device__ symbols.
    float *p_h0, *p_h1, *p_agg, *p_Afac, *p_Bfac, *p_Tperm;
    cudaGetSymbolAddress((void**)&p_h0,    g_h0);
    cudaGetSymbolAddress((void**)&p_h1,    g_h1);
    cudaGetSymbolAddress((void**)&p_agg,   g_agg);
    cudaGetSymbolAddress((void**)&p_Afac,  g_Afac);
    cudaGetSymbolAddress((void**)&p_Bfac,  g_Bfac);
    cudaGetSymbolAddress((void**)&p_Tperm, g_Tperm);

    const int SMEM128 = 4*128*((EMB+8)/2)*4;
    const int SMEM64  = 4*128*((IN_DIM+8)/2)*4;
    cudaFuncSetAttribute(gemm_bf16, cudaFuncAttributeMaxDynamicSharedMemorySize, SMEM128);

    const int  rtiles = (N_NODES + 127) / 128;       // 157
    const dim3 g128(1, rtiles);
    const dim3 g512(4, rtiles);
    const int  agg_blocks = (N_NODES + 7) / 8;
    const int  pe_blocks  = (N_EDGES + 255) / 256;   // 1250

    init_kernel<<<80, 256>>>();
    hist_kernel<<<640, 256>>>(dst);
    scan_kernel<<<1, 1024>>>();
    fill_kernel<<<640, 256>>>(src, dst);

    // ----- encoder GIN stack (att = 1) -----
    agg_kernel<<<agg_blocks, 256>>>(x, p_agg, nullptr, IN_DIM);
    w_prep<<<16, 256>>>(enc_W0, IN_DIM, EMB);
    gemm_bf16<<<g128, 256, SMEM64>>>(x, p_agg, enc_b0, p_h0,
                                     N_NODES, IN_DIM, EMB, 1);
    float* hcur = p_h0; float* hnxt = p_h1;
    for (int l = 0; l < 4; l++) {
        agg_kernel<<<agg_blocks, 256>>>(hcur, p_agg, nullptr, EMB);
        w_prep<<<32, 256>>>(enc_W + l*EMB*EMB, EMB, EMB);
        gemm_bf16<<<g128, 256, SMEM128>>>(hcur, p_agg, enc_b + l*EMB, hnxt,
                                          N_NODES, EMB, EMB, 1);
        float* t = hcur; hcur = hnxt; hnxt = t;
    }

    // ----- edge attention (factored): A = h@W1[:128], B = h@W1[128:] -----
    w_prep<<<128, 256>>>(ea_W1, EMB, HID);
    gemm_bf16<<<g512, 256, SMEM128>>>(hcur, nullptr, nullptr, p_Afac,
                                      N_NODES, EMB, HID, 0);
    w_prep<<<128, 256>>>(ea_W1 + EMB*HID, EMB, HID);
    gemm_bf16<<<g512, 256, SMEM128>>>(hcur, nullptr, nullptr, p_Bfac,
                                      N_NODES, EMB, HID, 0);
    edge_pe_kernel<<<pe_blocks, 256>>>(ea_b1, ea_W2, ea_b2);

    finalize_kernel<<<1, 1>>>();
    sinkhorn_kernel<<<SK_BLOCKS, SK_THREADS>>>(u);

    // ----- classifier GIN stack (att = T, slot-ordered) -----
    agg_kernel<<<agg_blocks, 256>>>(x, p_agg, p_Tperm, IN_DIM);
    w_prep<<<16, 256>>>(cls_W0, IN_DIM, EMB);
    gemm_bf16<<<g128, 256, SMEM64>>>(x, p_agg, cls_b0, p_h0,
                                     N_NODES, IN_DIM, EMB, 1);
    hcur = p_h0; hnxt = p_h1;
    for (int l = 0; l < 4; l++) {
        agg_kernel<<<agg_blocks, 256>>>(hcur, p_agg, p_Tperm, EMB);
        w_prep<<<32, 256>>>(cls_W + l*EMB*EMB, EMB, EMB);
        gemm_bf16<<<g128, 256, SMEM128>>>(hcur, p_agg, cls_b + l*EMB, hnxt,
                                          N_NODES, EMB, EMB, 1);
        float* t = hcur; hcur = hnxt; hnxt = t;
    }

    // ----- mean pool + head -----
    colsum_kernel<<<160, EMB>>>(hcur);
    head_kernel<<<1, EMB>>>(head_W, head_b, (float*)d_out);
}

// round 17
// speedup vs baseline: 1.0370x; 1.0370x over previous
#include <cuda_runtime.h>
#include <math.h>
#include <stdint.h>

#define N_NODES 20000
#define N_EDGES 320000
#define IN_DIM  64
#define EMB     128
#define OUT_DIM 10
#define HID     512
#define RATIO_F 0.25
#define EPSF    1e-20f

// weight-table offsets (u32 units) in g_Wth/g_Wtl
#define OFF_ENC0  0
#define OFF_ENC(l)  (4096 + (l)*8192)
#define OFF_EA_A  36864
#define OFF_EA_B  69632
#define OFF_CLS0  102400
#define OFF_CLS(l)  (106496 + (l)*8192)
#define WTAB_SIZE 139264

// ---------------- scratch (static, no allocs) ----------------
__device__ float g_h0[N_NODES*EMB];
__device__ float g_h1[N_NODES*EMB];
__device__ float g_Afac[N_NODES*HID];
__device__ float g_Bfac[N_NODES*HID];
__device__ unsigned int g_Ah[N_NODES*64];   // split-bf16 A, hi (u32 = 2 bf16)
__device__ unsigned int g_Al[N_NODES*64];   // split-bf16 A, lo
__device__ float g_pe[N_EDGES];             // slot-ordered
__device__ float g_Tperm[N_EDGES];          // slot-ordered
__device__ int   g_counts[N_NODES];
__device__ int   g_rowptr[N_NODES+1];
__device__ int   g_cursor[N_NODES];
__device__ int   g_srcs[N_EDGES];
__device__ int   g_dsts[N_EDGES];
__device__ int   g_eids[N_EDGES];
__device__ double g_sum8[8], g_sumsq8[8];
__device__ float  g_pmin, g_pmax;
__device__ float  g_mean, g_invstd, g_csum;
__device__ double g_Ssum[32];
__device__ unsigned int g_barc;
__device__ volatile unsigned int g_barg;
__device__ double g_colsum[EMB];
__device__ unsigned int g_Wth[WTAB_SIZE];
__device__ unsigned int g_Wtl[WTAB_SIZE];

// ---------------- bf16 split helpers ----------------
__device__ __forceinline__ unsigned bf16rn(float f) {
    unsigned u = __float_as_uint(f);
    return (u + 0x7fffu + ((u >> 16) & 1u)) >> 16;
}
__device__ __forceinline__ void split2(float f, unsigned& hi, unsigned& lo) {
    hi = bf16rn(f);
    float fl = f - __uint_as_float(hi << 16);
    lo = bf16rn(fl);
}

// ---------------- init ----------------
__global__ void init_kernel() {
    int i = blockIdx.x*blockDim.x + threadIdx.x;
    int nt = gridDim.x*blockDim.x;
    for (int k = i; k < N_NODES; k += nt) { g_counts[k] = 0; g_cursor[k] = 0; }
    if (i < EMB) g_colsum[i] = 0.0;
    if (i < 32)  g_Ssum[i]   = 0.0;
    if (i < 8)   { g_sum8[i] = 0.0; g_sumsq8[i] = 0.0; }
    if (i == 0) {
        g_pmin =  3.0e38f; g_pmax = -3.0e38f;
        g_barc = 0u; g_barg = 0u;
    }
}

// ---------------- CSR build ----------------
__global__ void hist_kernel(const int* __restrict__ dst) {
    int i = blockIdx.x*blockDim.x + threadIdx.x;
    int nt = gridDim.x*blockDim.x;
    for (int e = i; e < N_EDGES; e += nt) atomicAdd(&g_counts[dst[e]], 1);
}

__global__ void scan_kernel() {
    __shared__ int s[1024];
    const int CH = (N_NODES + 1023) / 1024;  // 20
    int t = threadIdx.x;
    int lsum = 0;
    for (int i = 0; i < CH; i++) {
        int idx = t*CH + i;
        if (idx < N_NODES) lsum += g_counts[idx];
    }
    s[t] = lsum; __syncthreads();
    for (int off = 1; off < 1024; off <<= 1) {
        int v = (t >= off) ? s[t-off] : 0;
        __syncthreads();
        s[t] += v;
        __syncthreads();
    }
    int run = s[t] - lsum;
    for (int i = 0; i < CH; i++) {
        int idx = t*CH + i;
        if (idx < N_NODES) { g_rowptr[idx] = run; run += g_counts[idx]; }
    }
    if (t == 1023) g_rowptr[N_NODES] = s[1023];
}

__global__ void fill_kernel(const int* __restrict__ src, const int* __restrict__ dst) {
    int i = blockIdx.x*blockDim.x + threadIdx.x;
    int nt = gridDim.x*blockDim.x;
    for (int e = i; e < N_EDGES; e += nt) {
        int d = dst[e];
        int pos = atomicAdd(&g_cursor[d], 1);
        int slot = g_rowptr[d] + pos;
        g_srcs[slot] = src[e];
        g_dsts[slot] = d;
        g_eids[slot] = e;
    }
}

// ---------------- W prep: ALL weights, one launch ----------------
__device__ __forceinline__ void prep_one(const float* __restrict__ W,
                                         int K, int N_w, int off,
                                         int gtid, int gnt) {
    int kp2 = K >> 1;
    int total = N_w * kp2;
    for (int idx = gtid; idx < total; idx += gnt) {
        int n  = idx / kp2;
        int kp = idx - n*kp2;
        int k  = kp << 1;
        unsigned h0, l0, h1, l1;
        split2(W[(size_t)k*N_w + n],     h0, l0);
        split2(W[(size_t)(k+1)*N_w + n], h1, l1);
        g_Wth[off + idx] = h0 | (h1 << 16);
        g_Wtl[off + idx] = l0 | (l1 << 16);
    }
}

__global__ void w_prep_all(const float* __restrict__ enc_W0,
                           const float* __restrict__ enc_W,
                           const float* __restrict__ ea_W1,
                           const float* __restrict__ cls_W0,
                           const float* __restrict__ cls_W) {
    int gtid = blockIdx.x*blockDim.x + threadIdx.x;
    int gnt  = gridDim.x*blockDim.x;
    prep_one(enc_W0, IN_DIM, EMB, OFF_ENC0, gtid, gnt);
#pragma unroll
    for (int l = 0; l < 4; l++)
        prep_one(enc_W + l*EMB*EMB, EMB, EMB, OFF_ENC(l), gtid, gnt);
    prep_one(ea_W1,            EMB, HID, OFF_EA_A, gtid, gnt);
    prep_one(ea_W1 + EMB*HID,  EMB, HID, OFF_EA_B, gtid, gnt);
    prep_one(cls_W0, IN_DIM, EMB, OFF_CLS0, gtid, gnt);
#pragma unroll
    for (int l = 0; l < 4; l++)
        prep_one(cls_W + l*EMB*EMB, EMB, EMB, OFF_CLS(l), gtid, gnt);
}

// ---------------- aggregation + self-add + bf16 split: A = h[n] + sum w*h[src] ----------------
// Writes split-bf16 A rows directly to g_Ah/g_Al (row stride dim/2 u32).
__global__ void aggA_kernel(const float* __restrict__ h,
                            const float* __restrict__ Tw, int dim) {
    int warp = threadIdx.x >> 5, lane = threadIdx.x & 31;
    int n = blockIdx.x * 8 + warp;
    if (n >= N_NODES) return;
    int vdim = dim >> 2;
    bool active = lane < vdim;
    const float4* __restrict__ h4 = (const float4*)h;
    int beg = g_rowptr[n], end = g_rowptr[n+1];
    float4 a0 = {0,0,0,0}, a1 = a0, a2 = a0, a3 = a0;
    int j = beg;
    for (; j + 4 <= end; j += 4) {
        int s0 = g_srcs[j], s1 = g_srcs[j+1], s2 = g_srcs[j+2], s3 = g_srcs[j+3];
        float w0 = 1.f, w1 = 1.f, w2 = 1.f, w3 = 1.f;
        if (Tw) { w0 = Tw[j]; w1 = Tw[j+1]; w2 = Tw[j+2]; w3 = Tw[j+3]; }
        if (active) {
            float4 v0 = h4[s0*vdim + lane];
            float4 v1 = h4[s1*vdim + lane];
            float4 v2 = h4[s2*vdim + lane];
            float4 v3 = h4[s3*vdim + lane];
            a0.x = fmaf(w0, v0.x, a0.x); a0.y = fmaf(w0, v0.y, a0.y);
            a0.z = fmaf(w0, v0.z, a0.z); a0.w = fmaf(w0, v0.w, a0.w);
            a1.x = fmaf(w1, v1.x, a1.x); a1.y = fmaf(w1, v1.y, a1.y);
            a1.z = fmaf(w1, v1.z, a1.z); a1.w = fmaf(w1, v1.w, a1.w);
            a2.x = fmaf(w2, v2.x, a2.x); a2.y = fmaf(w2, v2.y, a2.y);
            a2.z = fmaf(w2, v2.z, a2.z); a2.w = fmaf(w2, v2.w, a2.w);
            a3.x = fmaf(w3, v3.x, a3.x); a3.y = fmaf(w3, v3.y, a3.y);
            a3.z = fmaf(w3, v3.z, a3.z); a3.w = fmaf(w3, v3.w, a3.w);
        }
    }
    for (; j < end; j++) {
        int s0 = g_srcs[j];
        float w0 = Tw ? Tw[j] : 1.f;
        if (active) {
            float4 v0 = h4[s0*vdim + lane];
            a0.x = fmaf(w0, v0.x, a0.x); a0.y = fmaf(w0, v0.y, a0.y);
            a0.z = fmaf(w0, v0.z, a0.z); a0.w = fmaf(w0, v0.w, a0.w);
        }
    }
    if (active) {
        float4 self = h4[(size_t)n*vdim + lane];
        float fx = self.x + a0.x + a1.x + a2.x + a3.x;
        float fy = self.y + a0.y + a1.y + a2.y + a3.y;
        float fz = self.z + a0.z + a1.z + a2.z + a3.z;
        float fw = self.w + a0.w + a1.w + a2.w + a3.w;
        unsigned h0,l0,h1,l1,h2,l2,h3,l3;
        split2(fx, h0, l0); split2(fy, h1, l1);
        split2(fz, h2, l2); split2(fw, h3, l3);
        ((uint2*)g_Ah)[(size_t)n*vdim + lane] = make_uint2(h0 | (h1<<16), h2 | (h3<<16));
        ((uint2*)g_Al)[(size_t)n*vdim + lane] = make_uint2(l0 | (l1<<16), l2 | (l3<<16));
    }
}

// ---------------- convert h (fp32) -> split-bf16 A (for ea GEMMs) ----------------
__global__ void convert_h(const float* __restrict__ h) {
    int i = blockIdx.x*blockDim.x + threadIdx.x;
    int nt = gridDim.x*blockDim.x;
    int total = N_NODES * (EMB/4);
    const float4* h4 = (const float4*)h;
    for (; i < total; i += nt) {
        float4 v = h4[i];
        unsigned h0,l0,h1,l1,h2,l2,h3,l3;
        split2(v.x, h0, l0); split2(v.y, h1, l1);
        split2(v.z, h2, l2); split2(v.w, h3, l3);
        ((uint2*)g_Ah)[i] = make_uint2(h0 | (h1<<16), h2 | (h3<<16));
        ((uint2*)g_Al)[i] = make_uint2(l0 | (l1<<16), l2 | (l3<<16));
    }
}

// ---------------- bf16 tensor-core GEMM: C = maybe_relu(A @ W [+bias]) ----------------
// A pre-split in g_Ah/g_Al (row stride K/2 u32). B from weight table at boff.
__device__ __forceinline__ void mma_bf16(float* c, unsigned a0, unsigned a1,
                                         unsigned a2, unsigned a3,
                                         unsigned b0, unsigned b1) {
    asm volatile(
        "mma.sync.aligned.m16n8k16.row.col.f32.bf16.bf16.f32 "
        "{%0,%1,%2,%3}, {%4,%5,%6,%7}, {%8,%9}, {%0,%1,%2,%3};"
        : "+f"(c[0]), "+f"(c[1]), "+f"(c[2]), "+f"(c[3])
        : "r"(a0), "r"(a1), "r"(a2), "r"(a3), "r"(b0), "r"(b1));
}

__global__ __launch_bounds__(256)
void gemm_bf16(const float* __restrict__ bias, float* __restrict__ C,
               int M, int K, int N_w, int do_relu, int boff) {
    extern __shared__ unsigned int sm[];
    const int KP2 = (K + 8) >> 1;
    unsigned int* Ah = sm;
    unsigned int* Al = Ah + 128*KP2;
    unsigned int* Bh = Al + 128*KP2;
    unsigned int* Bl = Bh + 128*KP2;
    const int tid = threadIdx.x;
    const int lane = tid & 31, wid = tid >> 5;
    const int row0 = blockIdx.y << 7;
    const int col0 = blockIdx.x << 7;
    const int kp2 = K >> 1;

    // B tile copy from weight table
    for (int idx = tid; idx < 128*kp2; idx += 256) {
        int nl = idx / kp2;
        int kp = idx - nl*kp2;
        unsigned src = (unsigned)(boff + (col0 + nl)*kp2 + kp);
        Bh[nl*KP2 + kp] = g_Wth[src];
        Bl[nl*KP2 + kp] = g_Wtl[src];
    }
    // A tile copy (pre-split)
    for (int idx = tid; idx < 128*kp2; idx += 256) {
        int m  = idx / kp2;
        int kp = idx - m*kp2;
        int gr = row0 + m;
        unsigned vh = 0u, vl = 0u;
        if (gr < M) {
            size_t src = (size_t)gr*kp2 + kp;
            vh = g_Ah[src];
            vl = g_Al[src];
        }
        Ah[m*KP2 + kp] = vh;
        Al[m*KP2 + kp] = vl;
    }
    __syncthreads();

    const int warp_m = wid >> 1, warp_n = wid & 1;
    const int rbase = warp_m << 5;
    const int nbase = warp_n << 6;
    const int g = lane >> 2, tg = lane & 3;
    const int ksteps = K >> 4;

    float c[2][8][4];
#pragma unroll
    for (int mt = 0; mt < 2; mt++)
#pragma unroll
        for (int nt = 0; nt < 8; nt++)
#pragma unroll
            for (int q = 0; q < 4; q++) c[mt][nt][q] = 0.f;

#pragma unroll
    for (int p = 0; p < 3; p++) {
        const unsigned int* Ap = (p == 2) ? Al : Ah;
        const unsigned int* Bp = (p == 1) ? Bl : Bh;
        for (int ks = 0; ks < ksteps; ks++) {
            int kb = (ks << 3) + tg;
            unsigned a[2][4];
#pragma unroll
            for (int mt = 0; mt < 2; mt++) {
                int r0 = rbase + (mt << 4) + g;
                a[mt][0] = Ap[r0*KP2 + kb];
                a[mt][1] = Ap[(r0+8)*KP2 + kb];
                a[mt][2] = Ap[r0*KP2 + kb + 4];
                a[mt][3] = Ap[(r0+8)*KP2 + kb + 4];
            }
            unsigned b[8][2];
#pragma unroll
            for (int nt = 0; nt < 8; nt++) {
                int n0 = nbase + (nt << 3) + g;
                b[nt][0] = Bp[n0*KP2 + kb];
                b[nt][1] = Bp[n0*KP2 + kb + 4];
            }
#pragma unroll
            for (int mt = 0; mt < 2; mt++)
#pragma unroll
                for (int nt = 0; nt < 8; nt++)
                    mma_bf16(c[mt][nt], a[mt][0], a[mt][1], a[mt][2], a[mt][3],
                             b[nt][0], b[nt][1]);
        }
    }

#pragma unroll
    for (int mt = 0; mt < 2; mt++) {
        int gr0 = row0 + rbase + (mt << 4) + g;
#pragma unroll
        for (int nt = 0; nt < 8; nt++) {
            int gc = col0 + nbase + (nt << 3) + (tg << 1);
            float bx = 0.f, by = 0.f;
            if (bias) { bx = bias[gc]; by = bias[gc+1]; }
            float v0 = c[mt][nt][0] + bx;
            float v1 = c[mt][nt][1] + by;
            float v2 = c[mt][nt][2] + bx;
            float v3 = c[mt][nt][3] + by;
            if (do_relu) {
                v0 = fmaxf(v0, 0.f); v1 = fmaxf(v1, 0.f);
                v2 = fmaxf(v2, 0.f); v3 = fmaxf(v3, 0.f);
            }
            if (gr0 < M)
                *reinterpret_cast<float2*>(C + (size_t)gr0*N_w + gc) = make_float2(v0, v1);
            if (gr0 + 8 < M)
                *reinterpret_cast<float2*>(C + (size_t)(gr0+8)*N_w + gc) = make_float2(v2, v3);
        }
    }
}

// ---------------- pe min/max atomics ----------------
__device__ void atomicMaxF(float* addr, float v) {
    int* ai = (int*)addr; int old = *ai;
    while (__int_as_float(old) < v) {
        int assumed = old;
        old = atomicCAS(ai, assumed, __float_as_int(v));
        if (old == assumed) break;
    }
}
__device__ void atomicMinF(float* addr, float v) {
    int* ai = (int*)addr; int old = *ai;
    while (__int_as_float(old) > v) {
        int assumed = old;
        old = atomicCAS(ai, assumed, __float_as_int(v));
        if (old == assumed) break;
    }
}

// ---------------- edge attention + fused stats (slot-ordered) ----------------
__global__ __launch_bounds__(256)
void edge_pe_kernel(const float* __restrict__ b1, const float* __restrict__ W2,
                    const float* __restrict__ b2) {
    const int lane = threadIdx.x & 31, warp = threadIdx.x >> 5;
    const int base = blockIdx.x*256 + warp*32;
    const float4* b1p = reinterpret_cast<const float4*>(b1);
    const float4* W2p = reinterpret_cast<const float4*>(W2);
    float4 b1r[4], w2r[4];
#pragma unroll
    for (int j = 0; j < 4; j++) {
        b1r[j] = b1p[lane + 32*j];
        w2r[j] = W2p[lane + 32*j];
    }
    float b2v = b2[0];
    double lsum = 0.0, lsq = 0.0;
    float mn = 3.0e38f, mx = -3.0e38f;
    for (int i = 0; i < 32; i++) {
        int slot = base + i;
        if (slot >= N_EDGES) break;
        int s = g_srcs[slot], d = g_dsts[slot];
        const float4* Ap = reinterpret_cast<const float4*>(&g_Afac[s*HID]);
        const float4* Bp = reinterpret_cast<const float4*>(&g_Bfac[d*HID]);
        float acc = 0.f;
#pragma unroll
        for (int j = 0; j < 4; j++) {
            int idx = lane + 32*j;
            float4 a = Ap[idx], b = Bp[idx];
            float z0 = fmaxf(a.x + b.x + b1r[j].x, 0.f);
            float z1 = fmaxf(a.y + b.y + b1r[j].y, 0.f);
            float z2 = fmaxf(a.z + b.z + b1r[j].z, 0.f);
            float z3 = fmaxf(a.w + b.w + b1r[j].w, 0.f);
            acc += z0*w2r[j].x + z1*w2r[j].y + z2*w2r[j].z + z3*w2r[j].w;
        }
#pragma unroll
        for (int off = 16; off > 0; off >>= 1)
            acc += __shfl_xor_sync(0xffffffffu, acc, off);
        if (lane == 0) {
            float pe = acc + b2v;
            g_pe[slot] = pe;
            lsum += pe; lsq += (double)pe*pe;
            mn = fminf(mn, pe); mx = fmaxf(mx, pe);
        }
    }
    __shared__ double ssum[8], ssq[8];
    __shared__ float smn[8], smx[8];
    if (lane == 0) { ssum[warp] = lsum; ssq[warp] = lsq; smn[warp] = mn; smx[warp] = mx; }
    __syncthreads();
    if (threadIdx.x == 0) {
        double ts = 0.0, tq = 0.0; float tmn = 3.0e38f, tmx = -3.0e38f;
#pragma unroll
        for (int w = 0; w < 8; w++) {
            ts += ssum[w]; tq += ssq[w];
            tmn = fminf(tmn, smn[w]); tmx = fmaxf(tmx, smx[w]);
        }
        atomicAdd(&g_sum8[blockIdx.x & 7], ts);
        atomicAdd(&g_sumsq8[blockIdx.x & 7], tq);
        atomicMinF(&g_pmin, tmn);
        atomicMaxF(&g_pmax, tmx);
    }
}

__global__ void finalize_kernel() {
    double s = 0.0, q = 0.0;
    for (int i = 0; i < 8; i++) { s += g_sum8[i]; q += g_sumsq8[i]; }
    double mean = s / (double)N_EDGES;
    double var = (q - s*s/(double)N_EDGES) / (double)(N_EDGES - 1);
    double istd = 1.0 / sqrt(var);
    g_mean = (float)mean;
    g_invstd = (float)istd;
    g_csum = (float)(((double)g_pmin + (double)g_pmax - 2.0*mean) * istd);
}

// ---------------- Sinkhorn: fused delta0, few blocks (cheap grid barrier) ----------------
#define SK_BLOCKS 33
#define SK_THREADS 256
#define SK_PER 38

__global__ void sinkhorn_kernel(const float* __restrict__ u) {
    const int stride = SK_BLOCKS * SK_THREADS;
    const int tid = blockIdx.x*blockDim.x + threadIdx.x;
    const float mean = g_mean, istd = g_invstd, cs = g_csum;
    float dv[SK_PER];
#pragma unroll
    for (int i = 0; i < SK_PER; i++) {
        int e = tid + i*stride;
        if (e < N_EDGES) {
            float pe = g_pe[e];
            float uu = u[g_eids[e]];
            float gmb = -logf(-logf(uu + EPSF) + EPSF);
            float att = (pe - mean) * istd;
            dv[i] = 2.f*(att + gmb) - cs;
        } else {
            dv[i] = -1.0e30f;
        }
    }
    __shared__ double sred[SK_THREADS];
    double K = 0.0;
    double Sfin = 0.0;
    for (int it = 0; it < 30; it++) {
        float Kf = (float)K;
        double s = 0.0;
#pragma unroll
        for (int i = 0; i < SK_PER; i++)
            s += 1.0f / (1.0f + __expf(-(dv[i] + Kf)));
        sred[threadIdx.x] = s;
        __syncthreads();
        for (int off = SK_THREADS/2; off > 0; off >>= 1) {
            if (threadIdx.x < off) sred[threadIdx.x] += sred[threadIdx.x + off];
            __syncthreads();
        }
        if (threadIdx.x == 0) atomicAdd(&g_Ssum[it], sred[0]);
        __threadfence();
        __syncthreads();
        if (threadIdx.x == 0) {
            unsigned my = atomicAdd(&g_barc, 1u);
            if (my == SK_BLOCKS - 1) {
                g_barc = 0u;
                __threadfence();
                g_barg = (unsigned)(it + 1);
            } else {
                while (g_barg < (unsigned)(it + 1)) { }
            }
        }
        __syncthreads();
        __threadfence();
        double S1 = ((volatile double*)g_Ssum)[it];
        if (it == 29) { Sfin = S1; break; }
        double S0 = (double)N_EDGES - S1;
        K += log(S0 / S1) + log(RATIO_F / (1.0 - RATIO_F));
        __syncthreads();
    }
    float Kf = (float)K;
    float scale = (float)(((double)N_EDGES * RATIO_F) / Sfin);
#pragma unroll
    for (int i = 0; i < SK_PER; i++) {
        int e = tid + i*stride;
        if (e < N_EDGES)
            g_Tperm[e] = scale / (1.f + __expf(-(dv[i] + Kf)));
    }
}

// ---------------- mean pool + head ----------------
__global__ void colsum_kernel(const float* __restrict__ h) {
    int t = threadIdx.x;
    double acc = 0.0;
    for (int r = blockIdx.x; r < N_NODES; r += gridDim.x)
        acc += h[r*EMB + t];
    atomicAdd(&g_colsum[t], acc);
}

__global__ void head_kernel(const float* __restrict__ head_W,
                            const float* __restrict__ head_b,
                            float* __restrict__ out) {
    __shared__ float rep[EMB];
    int t = threadIdx.x;
    rep[t] = (float)(g_colsum[t] / (double)N_NODES);
    __syncthreads();
    if (t < OUT_DIM) {
        float a = head_b[t];
        for (int d = 0; d < EMB; d++) a += rep[d] * head_W[d*OUT_DIM + t];
        out[t] = a;
    }
}

// ---------------- launch ----------------
extern "C" void kernel_launch(void* const* d_in, const int* in_sizes, int n_in,
                              void* d_out, int out_size) {
    const float* x       = (const float*)d_in[0];
    const int*   ei      = (const int*)  d_in[1];
    const float* u       = (const float*)d_in[2];
    const float* enc_W0  = (const float*)d_in[3];
    const float* enc_b0  = (const float*)d_in[4];
    const float* enc_W   = (const float*)d_in[5];
    const float* enc_b   = (const float*)d_in[6];
    const float* ea_W1   = (const float*)d_in[7];
    const float* ea_b1   = (const float*)d_in[8];
    const float* ea_W2   = (const float*)d_in[9];
    const float* ea_b2   = (const float*)d_in[10];
    const float* cls_W0  = (const float*)d_in[11];
    const float* cls_b0  = (const float*)d_in[12];
    const float* cls_W   = (const float*)d_in[13];
    const float* cls_b   = (const float*)d_in[14];
    const float* head_W  = (const float*)d_in[15];
    const float* head_b  = (const float*)d_in[16];
    const int* src = ei;
    const int* dst = ei + N_EDGES;

    // GB300/ATS: resolve real device addresses of __device__ symbols.
    float *p_h0, *p_h1, *p_Afac, *p_Bfac, *p_Tperm;
    cudaGetSymbolAddress((void**)&p_h0,    g_h0);
    cudaGetSymbolAddress((void**)&p_h1,    g_h1);
    cudaGetSymbolAddress((void**)&p_Afac,  g_Afac);
    cudaGetSymbolAddress((void**)&p_Bfac,  g_Bfac);
    cudaGetSymbolAddress((void**)&p_Tperm, g_Tperm);

    const int SMEM128 = 4*128*((EMB+8)/2)*4;
    cudaFuncSetAttribute(gemm_bf16, cudaFuncAttributeMaxDynamicSharedMemorySize, SMEM128);
    const int SMEM64  = 4*128*((IN_DIM+8)/2)*4;

    const int  rtiles = (N_NODES + 127) / 128;       // 157
    const dim3 g128(1, rtiles);
    const dim3 g512(4, rtiles);
    const int  agg_blocks = (N_NODES + 7) / 8;
    const int  pe_blocks  = (N_EDGES + 255) / 256;   // 1250

    init_kernel<<<80, 256>>>();
    hist_kernel<<<640, 256>>>(dst);
    scan_kernel<<<1, 1024>>>();
    fill_kernel<<<640, 256>>>(src, dst);
    w_prep_all<<<264, 256>>>(enc_W0, enc_W, ea_W1, cls_W0, cls_W);

    // ----- encoder GIN stack (att = 1) -----
    aggA_kernel<<<agg_blocks, 256>>>(x, nullptr, IN_DIM);
    gemm_bf16<<<g128, 256, SMEM64>>>(enc_b0, p_h0, N_NODES, IN_DIM, EMB, 1, OFF_ENC0);
    float* hcur = p_h0; float* hnxt = p_h1;
    for (int l = 0; l < 4; l++) {
        aggA_kernel<<<agg_blocks, 256>>>(hcur, nullptr, EMB);
        gemm_bf16<<<g128, 256, SMEM128>>>(enc_b + l*EMB, hnxt,
                                          N_NODES, EMB, EMB, 1, OFF_ENC(l));
        float* t = hcur; hcur = hnxt; hnxt = t;
    }

    // ----- edge attention (factored): A = h@W1[:128], B = h@W1[128:] -----
    convert_h<<<640, 256>>>(hcur);
    gemm_bf16<<<g512, 256, SMEM128>>>(nullptr, p_Afac, N_NODES, EMB, HID, 0, OFF_EA_A);
    gemm_bf16<<<g512, 256, SMEM128>>>(nullptr, p_Bfac, N_NODES, EMB, HID, 0, OFF_EA_B);
    edge_pe_kernel<<<pe_blocks, 256>>>(ea_b1, ea_W2, ea_b2);

    finalize_kernel<<<1, 1>>>();
    sinkhorn_kernel<<<SK_BLOCKS, SK_THREADS>>>(u);

    // ----- classifier GIN stack (att = T, slot-ordered) -----
    aggA_kernel<<<agg_blocks, 256>>>(x, p_Tperm, IN_DIM);
    gemm_bf16<<<g128, 256, SMEM64>>>(cls_b0, p_h0, N_NODES, IN_DIM, EMB, 1, OFF_CLS0);
    hcur = p_h0; hnxt = p_h1;
    for (int l = 0; l < 4; l++) {
        aggA_kernel<<<agg_blocks, 256>>>(hcur, p_Tperm, EMB);
        gemm_bf16<<<g128, 256, SMEM128>>>(cls_b + l*EMB, hnxt,
                                          N_NODES, EMB, EMB, 1, OFF_CLS(l));
        float* t = hcur; hcur = hnxt; hnxt = t;
    }

    // ----- mean pool + head -----
    colsum_kernel<<<160, EMB>>>(hcur);
    head_kernel<<<1, EMB>>>(head_W, head_b, (float*)d_out);
}